// round 4
// baseline (speedup 1.0000x reference)
#include <cuda_runtime.h>
#include <cstdint>

#define PS 32
#define NB 36
#define THREADS 256

// fp32 constants exactly as XLA materializes them
#define PI_F     3.14159274101257324219f   // (float)pi
#define TWOPI_F  6.28318548202514648438f   // (float)(2*pi)

__global__ __launch_bounds__(THREADS)
void orient_kernel(const float* __restrict__ x,
                   const float* __restrict__ gk,
                   float* __restrict__ out) {
    __shared__ __align__(16) float sp[PS * PS];
    __shared__ float hist[NB];

    const int b = blockIdx.x;
    const int tid = threadIdx.x;

    // Load the 32x32 patch: 1024 floats = 256 float4, one per thread (coalesced).
    const float4* px4 = reinterpret_cast<const float4*>(x + (size_t)b * (PS * PS));
    reinterpret_cast<float4*>(sp)[tid] = px4[tid];
    if (tid < NB) hist[tid] = 0.0f;
    __syncthreads();

    #pragma unroll
    for (int k = 0; k < 4; k++) {
        const int i = tid + k * THREADS;
        const int r = i >> 5;
        const int c = i & 31;

        // Replicate-padded central differences (exact fp32, matches reference)
        const float l  = sp[(r << 5) + (c == 0 ? 0 : c - 1)];
        const float rr = sp[(r << 5) + (c == 31 ? 31 : c + 1)];
        const float u  = sp[((r == 0 ? 0 : r - 1) << 5) + c];
        const float d  = sp[((r == 31 ? 31 : r + 1) << 5) + c];
        const float gx = __fmul_rn(0.5f, __fsub_rn(l, rr));
        const float gy = __fmul_rn(0.5f, __fsub_rn(u, d));

        // mag = sqrt(((gx*gx) + (gy*gy)) + 1e-10) * gk   -- exact ref op order, no fma
        const float s2  = __fadd_rn(__fadd_rn(__fmul_rn(gx, gx), __fmul_rn(gy, gy)), 1e-10f);
        const float mag = __fmul_rn(sqrtf(s2), gk[i]);

        // ori via the same libdevice __nv_atan2f the XLA reference uses
        const float ori = atan2f(gy, gx);

        // o_big = (36 * (ori + pi)) / (2*pi)   -- exact ref op order
        const float o  = __fdiv_rn(__fmul_rn(36.0f, __fadd_rn(ori, PI_F)), TWOPI_F);
        const float bo = floorf(o);
        const float wo1 = __fsub_rn(o, bo);
        const float w   = __fmul_rn(__fsub_rn(1.0f, wo1), mag);

        int ib = (int)bo;
        if (ib >= NB) ib -= NB;   // mod(bo0, 36): only bo==36 wraps
        if (ib < 0)   ib = 0;     // safety (cannot occur: o >= 0)
        atomicAdd(&hist[ib], w);
    }
    __syncthreads();

    // Smooth (0.33, 0.34, 0.33) with zero pad, first-max argmax, angle.
    // Skipping the /1024 is exactly argmax-equivalent (power-of-two scale).
    if (tid == 0) {
        float best = -1e30f;
        int bi = 0;
        #pragma unroll
        for (int i = 0; i < NB; i++) {
            const float lft = (i > 0)      ? hist[i - 1] : 0.0f;
            const float ctr = hist[i];
            const float rgt = (i < NB - 1) ? hist[i + 1] : 0.0f;
            const float sm = __fadd_rn(
                __fadd_rn(__fmul_rn(0.33f, lft), __fmul_rn(0.34f, ctr)),
                __fmul_rn(0.33f, rgt));
            if (sm > best) { best = sm; bi = i; }
        }
        const float fi = (float)bi;
        // angle = -((2*pi*idx)/36 - pi)  -- exact ref op order
        out[b] = -__fsub_rn(__fdiv_rn(__fmul_rn(TWOPI_F, fi), 36.0f), PI_F);
    }
}

extern "C" void kernel_launch(void* const* d_in, const int* in_sizes, int n_in,
                              void* d_out, int out_size) {
    const float* x  = (const float*)d_in[0];
    const float* gk = (const float*)d_in[1];
    float* out = (float*)d_out;
    const int B = in_sizes[0] / (PS * PS);
    orient_kernel<<<B, THREADS>>>(x, gk, out);
}

// round 6
// speedup vs baseline: 1.9068x; 1.9068x over previous
#include <cuda_runtime.h>
#include <cstdint>

#define PS 32
#define NB 36
#define WPB 8                    // warps (patches) per block
#define THREADS (WPB * 32)

// fp32 constants exactly as XLA materializes them
#define PI_F     3.14159274101257324219f   // (float)pi
#define TWOPI_F  6.28318548202514648438f   // (float)(2*pi)

__global__ __launch_bounds__(THREADS)
void orient_kernel(const float* __restrict__ x,
                   const float* __restrict__ gk,
                   float* __restrict__ out, int B) {
    __shared__ float hist[WPB][NB];

    const int warp = threadIdx.x >> 5;
    const int lane = threadIdx.x & 31;
    const int b = blockIdx.x * WPB + warp;
    if (b >= B) return;               // warp-independent: safe (no block syncs)

    float* h = hist[warp];
    h[lane] = 0.0f;
    if (lane < NB - 32) h[lane + 32] = 0.0f;
    __syncwarp();

    const float* px = x + (size_t)b * (PS * PS) + lane;
    const float* pg = gk + lane;

    // Rolling 4-register row buffer. Invariant entering iter r:
    //   buf[(r-1)&3] = row r-1 (clamped), buf[r&3] = row r, buf[(r+1)&3] = row r+1 (clamped)
    float buf[4];
    buf[0] = __ldg(px);               // row 0
    buf[1] = __ldg(px + PS);          // row 1
    buf[2] = __ldg(px + 2 * PS);      // row 2
    buf[3] = buf[0];                  // "row -1" = row 0 (replicate) for r=0

    #pragma unroll 4
    for (int r = 0; r < PS; r++) {
        // Prefetch row r+2 (clamped) — consumed at iteration r+1. Issue early.
        const int pr = (r + 2 < PS) ? (r + 2) : (PS - 1);
        const float nxt = __ldg(px + pr * PS);
        const float g   = __ldg(pg + r * PS);

        const float cur = buf[r & 3];
        const float up  = buf[(r + 3) & 3];   // row r-1 (or clamp)
        const float dn  = buf[(r + 1) & 3];   // row r+1 (or clamp)

        // shfl out-of-range returns own value => replicate clamp for free
        const float lft = __shfl_up_sync(0xffffffffu, cur, 1);
        const float rgt = __shfl_down_sync(0xffffffffu, cur, 1);

        // Exact reference fp32 op order (no fma contraction)
        const float gx = __fmul_rn(0.5f, __fsub_rn(lft, rgt));
        const float gy = __fmul_rn(0.5f, __fsub_rn(up, dn));
        const float s2 = __fadd_rn(__fadd_rn(__fmul_rn(gx, gx), __fmul_rn(gy, gy)), 1e-10f);
        const float mag = __fmul_rn(sqrtf(s2), g);
        const float ori = atan2f(gy, gx);

        // o_big = (36 * (ori + pi)) / (2*pi)
        const float o  = __fdiv_rn(__fmul_rn(36.0f, __fadd_rn(ori, PI_F)), TWOPI_F);
        const float bo = floorf(o);
        const float w  = __fmul_rn(__fsub_rn(1.0f, __fsub_rn(o, bo)), mag);

        int ib = (int)bo;
        if (ib >= NB) ib -= NB;       // only o==36 wraps (ori==+pi)
        atomicAdd(&h[ib], w);

        buf[(r + 2) & 3] = nxt;       // rotate after all reads of this iter
    }
    __syncwarp();

    // Smooth (0.33, 0.34, 0.33), zero-padded; first-max argmax over 36 bins,
    // parallel across the warp. Skipping /1024 is exactly argmax-equivalent.
    const float c0 = h[lane];
    const float l0 = (lane > 0) ? h[lane - 1] : 0.0f;
    const float r0 = h[lane + 1];     // lane 31 -> h[32] (real neighbor, not pad)
    float bv = __fadd_rn(__fadd_rn(__fmul_rn(0.33f, l0), __fmul_rn(0.34f, c0)),
                         __fmul_rn(0.33f, r0));
    int bi = lane;
    if (lane < NB - 32) {             // lanes 0..3 also handle bins 32..35
        const int i2 = lane + 32;
        const float c2 = h[i2];
        const float l2 = h[i2 - 1];
        const float r2 = (i2 < NB - 1) ? h[i2 + 1] : 0.0f;
        const float sm2 = __fadd_rn(__fadd_rn(__fmul_rn(0.33f, l2), __fmul_rn(0.34f, c2)),
                                    __fmul_rn(0.33f, r2));
        if (sm2 > bv) { bv = sm2; bi = i2; }  // i2 > lane: tie keeps lane (first-max)
    }
    #pragma unroll
    for (int off = 16; off > 0; off >>= 1) {
        const float ov = __shfl_xor_sync(0xffffffffu, bv, off);
        const int   oi = __shfl_xor_sync(0xffffffffu, bi, off);
        if (ov > bv || (ov == bv && oi < bi)) { bv = ov; bi = oi; }
    }

    if (lane == 0) {
        // angle = -((2*pi*idx)/36 - pi), exact ref op order
        out[b] = -__fsub_rn(__fdiv_rn(__fmul_rn(TWOPI_F, (float)bi), 36.0f), PI_F);
    }
}

extern "C" void kernel_launch(void* const* d_in, const int* in_sizes, int n_in,
                              void* d_out, int out_size) {
    const float* x  = (const float*)d_in[0];
    const float* gk = (const float*)d_in[1];
    float* out = (float*)d_out;
    const int B = in_sizes[0] / (PS * PS);
    const int grid = (B + WPB - 1) / WPB;
    orient_kernel<<<grid, THREADS>>>(x, gk, out, B);
}